// round 5
// baseline (speedup 1.0000x reference)
#include <cuda_runtime.h>
#include <cuda_fp16.h>
#include <cstdint>
#include <math.h>

// Problem constants
#define S_DIM 500
#define T_DIM 8
#define FO    64
#define CN    4096          // B*T*FO
#define KP    512           // padded spatial dim
#define KA_MAIN 1024        // A-side K (hi|lo concat)
#define K2A   384           // mix A-side K (3 blocks x 64, hi|lo)
#define K2B   192           // mix B-side K (hi only)
#define M2R   32000         // S * 64 rows of mix GEMM

// ---------------- device scratch (allocation-free) ----------------
__device__ float   g_Z   [S_DIM * CN];          // fp32 activations [s][n]
__device__ float   g_C   [1024 * CN];           // rows 0..499: As@Z ; 512..1011: As^2@Z
__device__ __half  g_Abig[1024 * KA_MAIN];      // [As; As2] A-side [hi(512)|lo(512)]
__device__ __half  g_BT  [KP * KP];             // As^T hi only
__device__ __half  g_Bhi [CN * KP];             // Z^T hi only [n][k]
__device__ __half  g_A2  [(size_t)M2R * K2A];   // [Zhi|Y1hi|Y2hi|Zlo|Y1lo|Y2lo]
__device__ __half  g_Ht  [3 * FO * K2B];        // per-layer H^T hi

// ---------------- helpers ----------------
static __device__ __forceinline__ uint32_t smem_u32(const void* p) {
    uint32_t a;
    asm("{ .reg .u64 t; cvta.to.shared.u64 t, %1; cvt.u32.u64 %0, t; }" : "=r"(a) : "l"(p));
    return a;
}
static __device__ __forceinline__ void split_h(float v, __half& h, __half& l) {
    h = __float2half_rn(v);
    l = __float2half_rn(v - __half2float(h));
}

#define CP_ASYNC16(s, g) asm volatile("cp.async.cg.shared.global [%0], [%1], 16;" :: "r"(s), "l"(g))
#define CP_COMMIT()      asm volatile("cp.async.commit_group;")
#define CP_WAIT0()       asm volatile("cp.async.wait_group 0;")
#define CP_WAIT1()       asm volatile("cp.async.wait_group 1;")

#define LDSM4(r0, r1, r2, r3, a)                                                     \
    asm volatile("ldmatrix.sync.aligned.m8n8.x4.shared.b16 {%0,%1,%2,%3}, [%4];"     \
        : "=r"(r0), "=r"(r1), "=r"(r2), "=r"(r3) : "r"(a))

#define MMA16816(d, a0, a1, a2, a3, b0, b1)                                          \
    asm volatile("mma.sync.aligned.m16n8k16.row.col.f32.f16.f16.f32 "                \
        "{%0,%1,%2,%3}, {%4,%5,%6,%7}, {%8,%9}, {%0,%1,%2,%3};"                      \
        : "+f"((d)[0]), "+f"((d)[1]), "+f"((d)[2]), "+f"((d)[3])                     \
        : "r"(a0), "r"(a1), "r"(a2), "r"(a3), "r"(b0), "r"(b1))

// smem row: 64 halves + 8 pad = 144 B (ldmatrix conflict-free)
#define SROW 144
#define ATILE_B (128 * SROW)        // 18432 bytes per 128x64 tile
#define BTILE2_B (64 * SROW)        // 9216

// ---------------------------------------------------------------------------
// tg_main: C[128x128 tile] = (Ahi + Alo)[m,2*KB] @ Bhi[n,KB]^T
// A row: [hi(KB) | lo(KB)] halves, stride 2*KB. B row: KB halves.
// mode 0: fp32 C (ldc).  mode 1: write fp16 split into g_Abig rows 512+.
// BM=128 BN=128 BK=64, 256 thr, warps 2(M)x4(N).
// ---------------------------------------------------------------------------
__global__ __launch_bounds__(256)
void tg_main(const __half* __restrict__ A, const __half* __restrict__ B,
             float* __restrict__ C, int KB, int ldc, int mode)
{
    extern __shared__ char smem[];
    const uint32_t sb = smem_u32(smem);
    const int BUFSZ = 3 * ATILE_B;              // Ahi + Alo + B

    const int tid  = threadIdx.x;
    const int lane = tid & 31, w = tid >> 5;
    const int wm = w >> 2, wn = w & 3;          // 2 x 4 warps
    const int m0 = blockIdx.y * 128;
    const int n0 = blockIdx.x * 128;
    const int lda = 2 * KB;
    const int NIT = KB >> 6;

    uint32_t aOff[4], bOff[2];
    {
        const int acb = (lane >> 4) * 16;
        #pragma unroll
        for (int i = 0; i < 4; i++) {
            const int r = wm * 64 + i * 16 + ((lane >> 3) & 1) * 8 + (lane & 7);
            aOff[i] = (uint32_t)(r * SROW + acb);
        }
        const int bcb = ((lane >> 3) & 1) * 16;
        #pragma unroll
        for (int p = 0; p < 2; p++) {
            const int r = wn * 32 + p * 16 + (lane >> 4) * 8 + (lane & 7);
            bOff[p] = (uint32_t)(2 * ATILE_B + r * SROW + bcb);
        }
    }

    float acc[4][4][4];
    #pragma unroll
    for (int i = 0; i < 4; i++)
        #pragma unroll
        for (int j = 0; j < 4; j++)
            #pragma unroll
            for (int q = 0; q < 4; q++) acc[i][j][q] = 0.f;

    auto load_tiles = [&](int it, int bufi) {
        const uint32_t dst = sb + bufi * BUFSZ;
        const __half* gah = A + (size_t)m0 * lda + it * 64;
        const __half* gal = gah + KB;
        const __half* gb  = B + (size_t)n0 * KB + it * 64;
        #pragma unroll
        for (int i = 0; i < 4; i++) {
            const int ch = i * 256 + tid;       // 0..1023
            const int r = ch >> 3, c = ch & 7;
            CP_ASYNC16(dst + r * SROW + c * 16,               gah + (size_t)r * lda + c * 8);
            CP_ASYNC16(dst + ATILE_B + r * SROW + c * 16,     gal + (size_t)r * lda + c * 8);
            CP_ASYNC16(dst + 2 * ATILE_B + r * SROW + c * 16, gb  + (size_t)r * KB  + c * 8);
        }
    };

    load_tiles(0, 0);
    CP_COMMIT();

    int buf = 0;
    for (int it = 0; it < NIT; it++) {
        if (it + 1 < NIT) { load_tiles(it + 1, buf ^ 1); CP_COMMIT(); CP_WAIT1(); }
        else             { CP_WAIT0(); }
        __syncthreads();

        const uint32_t base = sb + buf * BUFSZ;
        #pragma unroll
        for (int ks = 0; ks < 4; ks++) {
            uint32_t am[4][4], bm[2][4];
            #pragma unroll
            for (int p = 0; p < 2; p++)
                LDSM4(bm[p][0], bm[p][1], bm[p][2], bm[p][3], base + bOff[p] + ks * 32);
            // hi pass
            #pragma unroll
            for (int i = 0; i < 4; i++)
                LDSM4(am[i][0], am[i][1], am[i][2], am[i][3], base + aOff[i] + ks * 32);
            #pragma unroll
            for (int i = 0; i < 4; i++)
                #pragma unroll
                for (int j = 0; j < 4; j++)
                    MMA16816(acc[i][j], am[i][0], am[i][1], am[i][2], am[i][3],
                             bm[j >> 1][(j & 1) * 2], bm[j >> 1][(j & 1) * 2 + 1]);
            // lo pass (same B frags)
            #pragma unroll
            for (int i = 0; i < 4; i++)
                LDSM4(am[i][0], am[i][1], am[i][2], am[i][3], base + ATILE_B + aOff[i] + ks * 32);
            #pragma unroll
            for (int i = 0; i < 4; i++)
                #pragma unroll
                for (int j = 0; j < 4; j++)
                    MMA16816(acc[i][j], am[i][0], am[i][1], am[i][2], am[i][3],
                             bm[j >> 1][(j & 1) * 2], bm[j >> 1][(j & 1) * 2 + 1]);
        }
        __syncthreads();
        buf ^= 1;
    }

    // epilogue
    #pragma unroll
    for (int i = 0; i < 4; i++) {
        #pragma unroll
        for (int h2 = 0; h2 < 2; h2++) {
            const int row = m0 + wm * 64 + i * 16 + (lane >> 2) + h2 * 8;
            #pragma unroll
            for (int j = 0; j < 4; j++) {
                const int col = n0 + wn * 32 + j * 8 + (lane & 3) * 2;
                const float v0 = acc[i][j][h2 * 2 + 0];
                const float v1 = acc[i][j][h2 * 2 + 1];
                if (mode == 0) {
                    *(float2*)&C[(size_t)row * ldc + col] = make_float2(v0, v1);
                } else {
                    // split-write As^2 into Abig rows 512..1023
                    __half h0, l0, h1, l1;
                    split_h(v0, h0, l0); split_h(v1, h1, l1);
                    __half* ap = g_Abig + (size_t)(512 + row) * KA_MAIN;
                    *(__half2*)(ap + col)       = __halves2half2(h0, h1);
                    *(__half2*)(ap + 512 + col) = __halves2half2(l0, l1);
                }
            }
        }
    }
}

// ---------------------------------------------------------------------------
// tg_mix: Z <- tanh( (A2hi+A2lo)[32000, 2*192] @ Ht[64,192]^T ), scatter to g_Z
// BM=128 BN=64 BK=64, warps 4(M)x2(N). grid 250.
// ---------------------------------------------------------------------------
__global__ __launch_bounds__(256)
void tg_mix(const __half* __restrict__ A, const __half* __restrict__ B)
{
    extern __shared__ char smem[];
    const uint32_t sb = smem_u32(smem);
    const int BUFSZ = 2 * ATILE_B + BTILE2_B;   // Ahi + Alo + B = 46080

    const int tid  = threadIdx.x;
    const int lane = tid & 31, w = tid >> 5;
    const int wm = w >> 1, wn = w & 1;          // 4 x 2 warps
    const int r0 = blockIdx.x * 128;
    const int NIT = 3;

    uint32_t aOff[2], bOff[2];
    {
        const int acb = (lane >> 4) * 16;
        #pragma unroll
        for (int i = 0; i < 2; i++) {
            const int r = wm * 32 + i * 16 + ((lane >> 3) & 1) * 8 + (lane & 7);
            aOff[i] = (uint32_t)(r * SROW + acb);
        }
        const int bcb = ((lane >> 3) & 1) * 16;
        #pragma unroll
        for (int p = 0; p < 2; p++) {
            const int r = wn * 32 + p * 16 + (lane >> 4) * 8 + (lane & 7);
            bOff[p] = (uint32_t)(2 * ATILE_B + r * SROW + bcb);
        }
    }

    float acc[2][4][4];
    #pragma unroll
    for (int i = 0; i < 2; i++)
        #pragma unroll
        for (int j = 0; j < 4; j++)
            #pragma unroll
            for (int q = 0; q < 4; q++) acc[i][j][q] = 0.f;

    auto load_tiles = [&](int it, int bufi) {
        const uint32_t dst = sb + bufi * BUFSZ;
        const __half* gah = A + (size_t)r0 * K2A + it * 64;
        const __half* gal = gah + K2B;
        const __half* gb  = B + it * 64;
        #pragma unroll
        for (int i = 0; i < 4; i++) {
            const int ch = i * 256 + tid;
            const int r = ch >> 3, c = ch & 7;
            CP_ASYNC16(dst + r * SROW + c * 16,           gah + (size_t)r * K2A + c * 8);
            CP_ASYNC16(dst + ATILE_B + r * SROW + c * 16, gal + (size_t)r * K2A + c * 8);
        }
        #pragma unroll
        for (int i = 0; i < 2; i++) {
            const int ch = i * 256 + tid;   // 0..511
            const int r = ch >> 3, c = ch & 7;
            CP_ASYNC16(dst + 2 * ATILE_B + r * SROW + c * 16, gb + (size_t)r * K2B + c * 8);
        }
    };

    load_tiles(0, 0);
    CP_COMMIT();

    int buf = 0;
    for (int it = 0; it < NIT; it++) {
        if (it + 1 < NIT) { load_tiles(it + 1, buf ^ 1); CP_COMMIT(); CP_WAIT1(); }
        else             { CP_WAIT0(); }
        __syncthreads();

        const uint32_t base = sb + buf * BUFSZ;
        #pragma unroll
        for (int ks = 0; ks < 4; ks++) {
            uint32_t am[2][4], bm[2][4];
            #pragma unroll
            for (int p = 0; p < 2; p++)
                LDSM4(bm[p][0], bm[p][1], bm[p][2], bm[p][3], base + bOff[p] + ks * 32);
            #pragma unroll
            for (int i = 0; i < 2; i++)
                LDSM4(am[i][0], am[i][1], am[i][2], am[i][3], base + aOff[i] + ks * 32);
            #pragma unroll
            for (int i = 0; i < 2; i++)
                #pragma unroll
                for (int j = 0; j < 4; j++)
                    MMA16816(acc[i][j], am[i][0], am[i][1], am[i][2], am[i][3],
                             bm[j >> 1][(j & 1) * 2], bm[j >> 1][(j & 1) * 2 + 1]);
            #pragma unroll
            for (int i = 0; i < 2; i++)
                LDSM4(am[i][0], am[i][1], am[i][2], am[i][3], base + ATILE_B + aOff[i] + ks * 32);
            #pragma unroll
            for (int i = 0; i < 2; i++)
                #pragma unroll
                for (int j = 0; j < 4; j++)
                    MMA16816(acc[i][j], am[i][0], am[i][1], am[i][2], am[i][3],
                             bm[j >> 1][(j & 1) * 2], bm[j >> 1][(j & 1) * 2 + 1]);
        }
        __syncthreads();
        buf ^= 1;
    }

    // epilogue: tanh + scatter into g_Z
    #pragma unroll
    for (int i = 0; i < 2; i++) {
        #pragma unroll
        for (int h2 = 0; h2 < 2; h2++) {
            const int rr = r0 + wm * 32 + i * 16 + (lane >> 2) + h2 * 8;
            const int s = rr >> 6, bt = rr & 63;
            float* zp = g_Z + (size_t)s * CN + bt * 64;
            #pragma unroll
            for (int j = 0; j < 4; j++) {
                const int col = wn * 32 + j * 8 + (lane & 3) * 2;
                zp[col]     = tanhf(acc[i][j][h2 * 2 + 0]);
                zp[col + 1] = tanhf(acc[i][j][h2 * 2 + 1]);
            }
        }
    }
}

// ---------------------------------------------------------------------------
// k_split_as: As -> Abig rows 0..511 ([hi|lo]) + BT (As^T hi only)
// ---------------------------------------------------------------------------
__global__ __launch_bounds__(256)
void k_split_as(const float* __restrict__ As)
{
    __shared__ float tile[32][33];
    const int tid = threadIdx.x;
    const int tr = tid >> 5, tc = tid & 31;
    const int r0 = blockIdx.y * 32, c0 = blockIdx.x * 32;

    #pragma unroll
    for (int ii = 0; ii < 4; ii++) {
        const int r = r0 + tr + ii * 8, c = c0 + tc;
        float v = (r < S_DIM && c < S_DIM) ? As[r * S_DIM + c] : 0.f;
        __half h, l; split_h(v, h, l);
        __half* ap = g_Abig + (size_t)r * KA_MAIN;
        ap[c] = h; ap[512 + c] = l;
        tile[tr + ii * 8][tc] = v;
    }
    __syncthreads();
    #pragma unroll
    for (int ii = 0; ii < 4; ii++) {
        const int a = tr + ii * 8;
        g_BT[(size_t)(c0 + a) * KP + r0 + tc] = __float2half_rn(tile[tc][a]);
    }
}

// ---------------------------------------------------------------------------
// k_splitT_z: Z[500,4096] -> Bhi[4096][512] (transpose, fp16 hi only)
// ---------------------------------------------------------------------------
__global__ __launch_bounds__(256)
void k_splitT_z()
{
    __shared__ float tile[32][33];
    const int tid = threadIdx.x;
    const int tr = tid >> 5, tc = tid & 31;
    const int r0 = blockIdx.y * 32;   // s
    const int c0 = blockIdx.x * 32;   // n

    #pragma unroll
    for (int ii = 0; ii < 4; ii++) {
        const int r = r0 + tr + ii * 8;
        tile[tr + ii * 8][tc] = (r < S_DIM) ? g_Z[(size_t)r * CN + c0 + tc] : 0.f;
    }
    __syncthreads();
    #pragma unroll
    for (int ii = 0; ii < 4; ii++) {
        const int a = tr + ii * 8;
        g_Bhi[(size_t)(c0 + a) * KP + r0 + tc] = __float2half_rn(tile[tc][a]);
    }
}

// ---------------------------------------------------------------------------
// k_ht: per-layer H -> Ht[64][192] hi only (B side). grid 3.
// ---------------------------------------------------------------------------
__global__ __launch_bounds__(256)
void k_ht(const float* __restrict__ H)
{
    const int l = blockIdx.x;
    for (int idx = threadIdx.x; idx < 3 * 64 * 64; idx += 256) {
        const int seg = idx >> 12, rem = idx & 4095;
        const int f = rem >> 6, g = rem & 63;
        const float v = H[l * 12288 + seg * 4096 + f * 64 + g];
        g_Ht[(size_t)l * FO * K2B + (size_t)g * K2B + seg * 64 + f] = __float2half_rn(v);
    }
}

// ---------------------------------------------------------------------------
// k_inproj
// ---------------------------------------------------------------------------
__global__ __launch_bounds__(256)
void k_inproj(const float* __restrict__ x, const float* __restrict__ W1,
              const float* __restrict__ b1)
{
    __shared__ float ws[FO][33];
    __shared__ float xs[50][32];
    __shared__ float bs[FO];

    const int tid = threadIdx.x;
    const int bt  = blockIdx.x;
    const int s0  = blockIdx.y * 50;

    for (int idx = tid; idx < FO * 32; idx += 256)
        ws[idx >> 5][idx & 31] = W1[idx];
    if (tid < FO) bs[tid] = b1[tid];
    const float* xp = x + (bt * S_DIM + s0) * 32;
    for (int idx = tid; idx < 50 * 32; idx += 256)
        xs[idx >> 5][idx & 31] = xp[idx];
    __syncthreads();

    const int f   = tid & 63;
    const int sl0 = tid >> 6;
    for (int sl = sl0; sl < 50; sl += 4) {
        float acc = bs[f];
        #pragma unroll
        for (int i = 0; i < 32; i++)
            acc += xs[sl][i] * ws[f][i];
        g_Z[(size_t)(s0 + sl) * CN + bt * FO + f] = acc;
    }
}

// ---------------------------------------------------------------------------
// k_comb: temporal mixing; writes mix A-operand g_A2 (fp16 2-split) directly
// grid 1000 x 256 thr (4 (b,s) groups per CTA)
// ---------------------------------------------------------------------------
__global__ __launch_bounds__(256)
void k_comb(const float* __restrict__ At, const float* __restrict__ sv)
{
    __shared__ float sAt[64];
    const int tid = threadIdx.x;
    if (tid < 64) sAt[tid] = At[tid];
    __syncthreads();

    const int g  = tid >> 6, f = tid & 63;
    const int bx = blockIdx.x * 4 + g;      // 0..3999
    const int b  = bx / 500;
    const int s  = bx - b * 500;

    const size_t base = (size_t)s * CN + b * (T_DIM * FO) + f;
    const size_t m2off = (size_t)KP * CN;

    float m0[8], m1v[8], m2v[8];
    #pragma unroll
    for (int t = 0; t < 8; t++) {
        m0[t]  = g_Z[base + t * 64];
        m1v[t] = g_C[base + t * 64];
        m2v[t] = g_C[m2off + base + t * 64];
    }
    const float s0 = sv[0], s1 = sv[1], s2 = sv[2], s3 = sv[3];
    const float c00 = s0 * s0, c01 = 2.f * s0 * s1, c02 = s1 * s1;
    const float c10 = 2.f * s0 * s2, c11 = 2.f * (s0 * s3 + s1 * s2), c12 = 2.f * s1 * s3;
    const float c20 = s2 * s2, c21 = 2.f * s2 * s3, c22 = s3 * s3;

    float n10[8], n11[8], n12[8];
    #pragma unroll
    for (int t = 0; t < 8; t++) {
        float a0 = 0.f, a1 = 0.f, a2 = 0.f;
        #pragma unroll
        for (int u = 0; u < 8; u++) {
            const float w = sAt[t * 8 + u];
            a0 += w * m0[u]; a1 += w * m1v[u]; a2 += w * m2v[u];
        }
        n10[t] = a0; n11[t] = a1; n12[t] = a2;
    }
    #pragma unroll
    for (int t = 0; t < 8; t++) {
        float a0 = 0.f, a1 = 0.f, a2 = 0.f;
        #pragma unroll
        for (int u = 0; u < 8; u++) {
            const float w = sAt[t * 8 + u];
            a0 += w * n10[u]; a1 += w * n11[u]; a2 += w * n12[u];
        }
        const float y1 = s0 * m0[t] + s1 * m1v[t] + s2 * n10[t] + s3 * n11[t];
        const float y2 = c00 * m0[t] + c01 * m1v[t] + c02 * m2v[t]
                       + c10 * n10[t] + c11 * n11[t] + c12 * n12[t]
                       + c20 * a0 + c21 * a1 + c22 * a2;

        __half* ap = g_A2 + (size_t)(s * 64 + b * 8 + t) * K2A;
        __half h, lo;
        split_h(m0[t], h, lo);  ap[f]       = h; ap[192 + f] = lo;
        split_h(y1, h, lo);     ap[64 + f]  = h; ap[256 + f] = lo;
        split_h(y2, h, lo);     ap[128 + f] = h; ap[320 + f] = lo;
    }
}

// ---------------------------------------------------------------------------
// k_out
// ---------------------------------------------------------------------------
__global__ __launch_bounds__(64)
void k_out(const float* __restrict__ W2, const float* __restrict__ b2,
           const float* __restrict__ merge, float* __restrict__ out)
{
    __shared__ float su[64];
    __shared__ float sm[8];
    const int tid = threadIdx.x;
    const int bx  = blockIdx.x;
    const int b   = bx / 500;
    const int s   = bx - b * 500;
    if (tid < 8) sm[tid] = merge[tid];
    __syncthreads();

    const size_t base = (size_t)s * CN + b * (T_DIM * FO) + tid;
    float acc = 0.f, msum = 0.f;
    #pragma unroll
    for (int t = 0; t < 8; t++) {
        acc  += sm[t] * g_Z[base + t * 64];
        msum += sm[t];
    }
    su[tid] = acc;
    __syncthreads();

    float o = msum * b2[tid];
    const float* w = W2 + tid * 64;
    #pragma unroll 8
    for (int f = 0; f < 64; f++) o += w[f] * su[f];
    out[bx * 64 + tid] = o;
}

// ---------------------------------------------------------------------------
extern "C" void kernel_launch(void* const* d_in, const int* in_sizes, int n_in,
                              void* d_out, int out_size)
{
    const float* x     = (const float*)d_in[0];
    const float* At    = (const float*)d_in[1];
    const float* As    = (const float*)d_in[2];
    const float* sv    = (const float*)d_in[3];
    const float* H     = (const float*)d_in[4];
    const float* W1    = (const float*)d_in[5];
    const float* b1    = (const float*)d_in[6];
    const float* W2    = (const float*)d_in[7];
    const float* b2    = (const float*)d_in[8];
    const float* merge = (const float*)d_in[9];
    float* out = (float*)d_out;

    const int SM_MAIN = 2 * (3 * ATILE_B);               // 110592
    const int SM_MIX  = 2 * (2 * ATILE_B + BTILE2_B);    // 92160
    cudaFuncSetAttribute(tg_main, cudaFuncAttributeMaxDynamicSharedMemorySize, SM_MAIN);
    cudaFuncSetAttribute(tg_mix,  cudaFuncAttributeMaxDynamicSharedMemorySize, SM_MIX);

    __half *Abig, *BT, *Bhi, *A2, *Ht;
    float *Cp;
    cudaGetSymbolAddress((void**)&Abig, g_Abig);
    cudaGetSymbolAddress((void**)&BT,   g_BT);
    cudaGetSymbolAddress((void**)&Bhi,  g_Bhi);
    cudaGetSymbolAddress((void**)&A2,   g_A2);
    cudaGetSymbolAddress((void**)&Ht,   g_Ht);
    cudaGetSymbolAddress((void**)&Cp,   g_C);

    k_ht<<<3, 256>>>(H);                                       // 0
    k_split_as<<<dim3(16, 16), 256>>>(As);                     // 1
    // As2 = As @ As (M=512,N=512), epilogue writes split into Abig rows 512+
    tg_main<<<dim3(4, 4), 256, SM_MAIN>>>(Abig, BT, Cp, KP, KP, 1);   // 2
    k_inproj<<<dim3(64, 10), 256>>>(x, W1, b1);                // 3

    for (int l = 0; l < 3; l++) {
        k_splitT_z<<<dim3(128, 16), 256>>>();                  // 4 (l=0)
        // C[1024,4096] = [As;As2] @ Z^T
        tg_main<<<dim3(32, 8), 256, SM_MAIN>>>(Abig, Bhi, Cp, KP, CN, 0);  // 5 (l=0) <- profiled
        k_comb<<<1000, 256>>>(At, sv);
        tg_mix<<<250, 256, SM_MIX>>>(A2, Ht + (size_t)l * FO * K2B);
    }

    k_out<<<4000, 64>>>(W2, b2, merge, out);
}

// round 6
// speedup vs baseline: 1.3335x; 1.3335x over previous
#include <cuda_runtime.h>
#include <cuda_fp16.h>
#include <cstdint>
#include <math.h>

// Problem constants
#define S_DIM 500
#define T_DIM 8
#define FO    64
#define CN    4096          // B*T*FO
#define KP    512           // padded spatial dim
#define KC    1024          // concat K for main GEMM: [hi(512)|lo(512)] / [Zhi|Zhi]
#define K2A   384           // mix K concat: [Zhi|Y1hi|Y2hi|Zlo|Y1lo|Y2lo]
#define M2R   32000         // S * 64 rows of mix GEMM

// ---------------- device scratch (allocation-free) ----------------
__device__ float   g_Z   [S_DIM * CN];          // fp32 activations [s][n]
__device__ float   g_C   [1024 * CN];           // rows 0..499: As@Z ; 512..1011: As^2@Z
__device__ __half  g_Abig[1024 * KC];           // [As; As2] rows, row = [hi|lo]
__device__ __half  g_BT  [KP * KC];             // As^T rows, row = [hi|hi]
__device__ __half  g_Bhi [CN * KC];             // Z^T rows, row = [hi|hi]
__device__ __half  g_A2  [(size_t)M2R * K2A];   // mix A operand
__device__ __half  g_Ht  [3 * FO * K2A];        // per-layer H^T, row = [H0|H1|H2|H0|H1|H2]

// ---------------- helpers ----------------
static __device__ __forceinline__ uint32_t smem_u32(const void* p) {
    uint32_t a;
    asm("{ .reg .u64 t; cvta.to.shared.u64 t, %1; cvt.u32.u64 %0, t; }" : "=r"(a) : "l"(p));
    return a;
}
static __device__ __forceinline__ void split_h(float v, __half& h, __half& l) {
    h = __float2half_rn(v);
    l = __float2half_rn(v - __half2float(h));
}

#define CP_ASYNC16(s, g) asm volatile("cp.async.cg.shared.global [%0], [%1], 16;" :: "r"(s), "l"(g))
#define CP_COMMIT()      asm volatile("cp.async.commit_group;")
#define CP_WAIT0()       asm volatile("cp.async.wait_group 0;")
#define CP_WAIT1()       asm volatile("cp.async.wait_group 1;")

#define LDSM4(r0, r1, r2, r3, a)                                                     \
    asm volatile("ldmatrix.sync.aligned.m8n8.x4.shared.b16 {%0,%1,%2,%3}, [%4];"     \
        : "=r"(r0), "=r"(r1), "=r"(r2), "=r"(r3) : "r"(a))

#define MMA16816(d, a0, a1, a2, a3, b0, b1)                                          \
    asm volatile("mma.sync.aligned.m16n8k16.row.col.f32.f16.f16.f32 "                \
        "{%0,%1,%2,%3}, {%4,%5,%6,%7}, {%8,%9}, {%0,%1,%2,%3};"                      \
        : "+f"((d)[0]), "+f"((d)[1]), "+f"((d)[2]), "+f"((d)[3])                     \
        : "r"(a0), "r"(a1), "r"(a2), "r"(a3), "r"(b0), "r"(b1))

// smem row: 64 halves + 8 pad = 144 B (ldmatrix conflict-free)
#define SROW 144
#define ATILE_B (128 * SROW)        // 18432 bytes per 128x64 tile
#define BTILE2_B (64 * SROW)        // 9216

// ---------------------------------------------------------------------------
// tg_main: C[128x128 tile] = A[m,K] @ B[n,K]^T  (fp16, fp32 acc)
// mode 0: fp32 C (ldc).  mode 1: write fp16 split into g_Abig rows 512+.
// BM=128 BN=128 BK=64, 256 thr, warps 2(M)x4(N).
// ---------------------------------------------------------------------------
__global__ __launch_bounds__(256)
void tg_main(const __half* __restrict__ A, const __half* __restrict__ B,
             float* __restrict__ C, int K, int ldc, int mode)
{
    extern __shared__ char smem[];
    const uint32_t sb = smem_u32(smem);
    const int BUFSZ = 2 * ATILE_B;              // A + B per buffer

    const int tid  = threadIdx.x;
    const int lane = tid & 31, w = tid >> 5;
    const int wm = w >> 2, wn = w & 3;          // 2 x 4 warps
    const int m0 = blockIdx.y * 128;
    const int n0 = blockIdx.x * 128;
    const int NIT = K >> 6;

    uint32_t aOff[4], bOff[2];
    {
        const int acb = (lane >> 4) * 16;
        #pragma unroll
        for (int i = 0; i < 4; i++) {
            const int r = wm * 64 + i * 16 + ((lane >> 3) & 1) * 8 + (lane & 7);
            aOff[i] = (uint32_t)(r * SROW + acb);
        }
        const int bcb = ((lane >> 3) & 1) * 16;
        #pragma unroll
        for (int p = 0; p < 2; p++) {
            const int r = wn * 32 + p * 16 + (lane >> 4) * 8 + (lane & 7);
            bOff[p] = (uint32_t)(ATILE_B + r * SROW + bcb);
        }
    }

    float acc[4][4][4];
    #pragma unroll
    for (int i = 0; i < 4; i++)
        #pragma unroll
        for (int j = 0; j < 4; j++)
            #pragma unroll
            for (int q = 0; q < 4; q++) acc[i][j][q] = 0.f;

    auto load_tiles = [&](int it, int bufi) {
        const uint32_t dst = sb + bufi * BUFSZ;
        const __half* ga = A + (size_t)m0 * K + it * 64;
        const __half* gb = B + (size_t)n0 * K + it * 64;
        #pragma unroll
        for (int i = 0; i < 4; i++) {
            const int ch = i * 256 + tid;       // 0..1023
            const int r = ch >> 3, c = ch & 7;
            CP_ASYNC16(dst + r * SROW + c * 16,           ga + (size_t)r * K + c * 8);
            CP_ASYNC16(dst + ATILE_B + r * SROW + c * 16, gb + (size_t)r * K + c * 8);
        }
    };

    load_tiles(0, 0);
    CP_COMMIT();

    int buf = 0;
    for (int it = 0; it < NIT; it++) {
        if (it + 1 < NIT) { load_tiles(it + 1, buf ^ 1); CP_COMMIT(); CP_WAIT1(); }
        else             { CP_WAIT0(); }
        __syncthreads();

        const uint32_t base = sb + buf * BUFSZ;
        #pragma unroll
        for (int ks = 0; ks < 4; ks++) {
            uint32_t am[4][4], bm[2][4];
            #pragma unroll
            for (int i = 0; i < 4; i++)
                LDSM4(am[i][0], am[i][1], am[i][2], am[i][3], base + aOff[i] + ks * 32);
            #pragma unroll
            for (int p = 0; p < 2; p++)
                LDSM4(bm[p][0], bm[p][1], bm[p][2], bm[p][3], base + bOff[p] + ks * 32);
            #pragma unroll
            for (int i = 0; i < 4; i++)
                #pragma unroll
                for (int j = 0; j < 4; j++)
                    MMA16816(acc[i][j], am[i][0], am[i][1], am[i][2], am[i][3],
                             bm[j >> 1][(j & 1) * 2], bm[j >> 1][(j & 1) * 2 + 1]);
        }
        __syncthreads();
        buf ^= 1;
    }

    // epilogue
    #pragma unroll
    for (int i = 0; i < 4; i++) {
        #pragma unroll
        for (int h2 = 0; h2 < 2; h2++) {
            const int row = m0 + wm * 64 + i * 16 + (lane >> 2) + h2 * 8;
            #pragma unroll
            for (int j = 0; j < 4; j++) {
                const int col = n0 + wn * 32 + j * 8 + (lane & 3) * 2;
                const float v0 = acc[i][j][h2 * 2 + 0];
                const float v1 = acc[i][j][h2 * 2 + 1];
                if (mode == 0) {
                    *(float2*)&C[(size_t)row * ldc + col] = make_float2(v0, v1);
                } else {
                    __half h0, l0, h1, l1;
                    split_h(v0, h0, l0); split_h(v1, h1, l1);
                    __half* ap = g_Abig + (size_t)(512 + row) * KC;
                    *(__half2*)(ap + col)       = __halves2half2(h0, h1);
                    *(__half2*)(ap + 512 + col) = __halves2half2(l0, l1);
                }
            }
        }
    }
}

// ---------------------------------------------------------------------------
// tg_mix: Z <- tanh( A2[32000,384] @ Ht[64,384]^T ), scatter to g_Z
// BM=128 BN=64 BK=64, warps 4(M)x2(N). grid 250.
// ---------------------------------------------------------------------------
__global__ __launch_bounds__(256)
void tg_mix(const __half* __restrict__ A, const __half* __restrict__ B)
{
    extern __shared__ char smem[];
    const uint32_t sb = smem_u32(smem);
    const int BUFSZ = ATILE_B + BTILE2_B;   // 27648

    const int tid  = threadIdx.x;
    const int lane = tid & 31, w = tid >> 5;
    const int wm = w >> 1, wn = w & 1;      // 4 x 2 warps
    const int r0 = blockIdx.x * 128;
    const int K = K2A;
    const int NIT = K / 64;                 // 6

    uint32_t aOff[2], bOff[2];
    {
        const int acb = (lane >> 4) * 16;
        #pragma unroll
        for (int i = 0; i < 2; i++) {
            const int r = wm * 32 + i * 16 + ((lane >> 3) & 1) * 8 + (lane & 7);
            aOff[i] = (uint32_t)(r * SROW + acb);
        }
        const int bcb = ((lane >> 3) & 1) * 16;
        #pragma unroll
        for (int p = 0; p < 2; p++) {
            const int r = wn * 32 + p * 16 + (lane >> 4) * 8 + (lane & 7);
            bOff[p] = (uint32_t)(ATILE_B + r * SROW + bcb);
        }
    }

    float acc[2][4][4];
    #pragma unroll
    for (int i = 0; i < 2; i++)
        #pragma unroll
        for (int j = 0; j < 4; j++)
            #pragma unroll
            for (int q = 0; q < 4; q++) acc[i][j][q] = 0.f;

    auto load_tiles = [&](int it, int bufi) {
        const uint32_t dst = sb + bufi * BUFSZ;
        const __half* ga = A + (size_t)r0 * K + it * 64;
        const __half* gb = B + it * 64;
        #pragma unroll
        for (int i = 0; i < 4; i++) {
            const int ch = i * 256 + tid;
            const int r = ch >> 3, c = ch & 7;
            CP_ASYNC16(dst + r * SROW + c * 16, ga + (size_t)r * K + c * 8);
        }
        #pragma unroll
        for (int i = 0; i < 2; i++) {
            const int ch = i * 256 + tid;   // 0..511
            const int r = ch >> 3, c = ch & 7;
            CP_ASYNC16(dst + ATILE_B + r * SROW + c * 16, gb + (size_t)r * K + c * 8);
        }
    };

    load_tiles(0, 0);
    CP_COMMIT();

    int buf = 0;
    for (int it = 0; it < NIT; it++) {
        if (it + 1 < NIT) { load_tiles(it + 1, buf ^ 1); CP_COMMIT(); CP_WAIT1(); }
        else             { CP_WAIT0(); }
        __syncthreads();

        const uint32_t base = sb + buf * BUFSZ;
        #pragma unroll
        for (int ks = 0; ks < 4; ks++) {
            uint32_t am[2][4], bm[2][4];
            #pragma unroll
            for (int i = 0; i < 2; i++)
                LDSM4(am[i][0], am[i][1], am[i][2], am[i][3], base + aOff[i] + ks * 32);
            #pragma unroll
            for (int p = 0; p < 2; p++)
                LDSM4(bm[p][0], bm[p][1], bm[p][2], bm[p][3], base + bOff[p] + ks * 32);
            #pragma unroll
            for (int i = 0; i < 2; i++)
                #pragma unroll
                for (int j = 0; j < 4; j++)
                    MMA16816(acc[i][j], am[i][0], am[i][1], am[i][2], am[i][3],
                             bm[j >> 1][(j & 1) * 2], bm[j >> 1][(j & 1) * 2 + 1]);
        }
        __syncthreads();
        buf ^= 1;
    }

    // epilogue: tanh + scatter into g_Z
    #pragma unroll
    for (int i = 0; i < 2; i++) {
        #pragma unroll
        for (int h2 = 0; h2 < 2; h2++) {
            const int rr = r0 + wm * 32 + i * 16 + (lane >> 2) + h2 * 8;
            const int s = rr >> 6, bt = rr & 63;
            float* zp = g_Z + (size_t)s * CN + bt * 64;
            #pragma unroll
            for (int j = 0; j < 4; j++) {
                const int col = wn * 32 + j * 8 + (lane & 3) * 2;
                zp[col]     = tanhf(acc[i][j][h2 * 2 + 0]);
                zp[col + 1] = tanhf(acc[i][j][h2 * 2 + 1]);
            }
        }
    }
}

// ---------------------------------------------------------------------------
// k_split_as: As -> Abig rows 0..511 ([hi|lo]) + BT (As^T, [hi|hi])
// ---------------------------------------------------------------------------
__global__ __launch_bounds__(256)
void k_split_as(const float* __restrict__ As)
{
    __shared__ float tile[32][33];
    const int tid = threadIdx.x;
    const int tr = tid >> 5, tc = tid & 31;
    const int r0 = blockIdx.y * 32, c0 = blockIdx.x * 32;

    #pragma unroll
    for (int ii = 0; ii < 4; ii++) {
        const int r = r0 + tr + ii * 8, c = c0 + tc;
        float v = (r < S_DIM && c < S_DIM) ? As[r * S_DIM + c] : 0.f;
        __half h, l; split_h(v, h, l);
        __half* ap = g_Abig + (size_t)r * KC;
        ap[c] = h; ap[512 + c] = l;
        tile[tr + ii * 8][tc] = v;
    }
    __syncthreads();
    #pragma unroll
    for (int ii = 0; ii < 4; ii++) {
        const int a = tr + ii * 8;
        const __half h = __float2half_rn(tile[tc][a]);
        __half* bp = g_BT + (size_t)(c0 + a) * KC;
        bp[r0 + tc] = h; bp[512 + r0 + tc] = h;
    }
}

// ---------------------------------------------------------------------------
// k_splitT_z: Z[500,4096] -> Bhi[4096][1024] (transpose, fp16 hi duplicated)
// ---------------------------------------------------------------------------
__global__ __launch_bounds__(256)
void k_splitT_z()
{
    __shared__ float tile[32][33];
    const int tid = threadIdx.x;
    const int tr = tid >> 5, tc = tid & 31;
    const int r0 = blockIdx.y * 32;   // s
    const int c0 = blockIdx.x * 32;   // n

    #pragma unroll
    for (int ii = 0; ii < 4; ii++) {
        const int r = r0 + tr + ii * 8;
        tile[tr + ii * 8][tc] = (r < S_DIM) ? g_Z[(size_t)r * CN + c0 + tc] : 0.f;
    }
    __syncthreads();
    #pragma unroll
    for (int ii = 0; ii < 4; ii++) {
        const int a = tr + ii * 8;
        const __half h = __float2half_rn(tile[tc][a]);
        __half* bp = g_Bhi + (size_t)(c0 + a) * KC;
        bp[r0 + tc] = h; bp[512 + r0 + tc] = h;
    }
}

// ---------------------------------------------------------------------------
// k_ht: per-layer H -> Ht[64][384] ([H0|H1|H2] duplicated). grid 3.
// ---------------------------------------------------------------------------
__global__ __launch_bounds__(256)
void k_ht(const float* __restrict__ H)
{
    const int l = blockIdx.x;
    for (int idx = threadIdx.x; idx < 3 * 64 * 64; idx += 256) {
        const int seg = idx >> 12, rem = idx & 4095;
        const int f = rem >> 6, g = rem & 63;
        const __half h = __float2half_rn(H[l * 12288 + seg * 4096 + f * 64 + g]);
        __half* hp = g_Ht + (size_t)l * FO * K2A + (size_t)g * K2A;
        hp[seg * 64 + f] = h; hp[192 + seg * 64 + f] = h;
    }
}

// ---------------------------------------------------------------------------
// k_inproj: Z[s,(b,t,f)] = x[b,t,s,:] @ W1^T + b1 ; also writes g_Bhi (l=0)
// W1 in registers; 13 parallel accumulator chains per thread.
// grid (64 bt, 10 s-chunks of 50), 256 threads.
// ---------------------------------------------------------------------------
__global__ __launch_bounds__(256)
void k_inproj(const float* __restrict__ x, const float* __restrict__ W1,
              const float* __restrict__ b1)
{
    __shared__ float xs[52][32];
    __shared__ __half hs[64][52];

    const int tid = threadIdx.x;
    const int bt  = blockIdx.x;
    const int s0  = blockIdx.y * 50;
    const int f   = tid & 63;
    const int sl0 = tid >> 6;       // 0..3

    float wreg[32];
    #pragma unroll
    for (int i = 0; i < 32; i++) wreg[i] = __ldg(&W1[f * 32 + i]);
    const float bias = __ldg(&b1[f]);

    const float* xp = x + (bt * S_DIM + s0) * 32;
    for (int idx = tid; idx < 50 * 32; idx += 256)
        xs[idx >> 5][idx & 31] = xp[idx];
    if (tid < 64) xs[50 + (tid >> 5)][tid & 31] = 0.f;   // zero pad rows 50,51
    __syncthreads();

    float acc[13];
    #pragma unroll
    for (int q = 0; q < 13; q++) acc[q] = bias;
    #pragma unroll
    for (int i = 0; i < 32; i++) {
        const float wv = wreg[i];
        #pragma unroll
        for (int q = 0; q < 13; q++)
            acc[q] += xs[q * 4 + sl0][i] * wv;
    }
    #pragma unroll
    for (int q = 0; q < 13; q++) {
        const int sl = q * 4 + sl0;
        if (sl < 50) {
            g_Z[(size_t)(s0 + sl) * CN + bt * 64 + f] = acc[q];
            hs[f][sl] = __float2half_rn(acc[q]);
        }
    }
    __syncthreads();

    // Bhi rows bt*64..bt*64+63, cols s0..s0+49, duplicated at +512
    for (int idx = tid; idx < 64 * 50; idx += 256) {
        const int r = idx / 50, c = idx - r * 50;
        const __half v = hs[r][c];
        __half* bp = g_Bhi + (size_t)(bt * 64 + r) * KC + s0 + c;
        bp[0] = v; bp[512] = v;
    }
}

// ---------------------------------------------------------------------------
// k_comb: temporal mixing; writes mix A-operand g_A2 (fp16 2-split)
// grid 1000 x 256 thr (4 (b,s) groups per CTA)
// ---------------------------------------------------------------------------
__global__ __launch_bounds__(256)
void k_comb(const float* __restrict__ At, const float* __restrict__ sv)
{
    __shared__ float sAt[64];
    const int tid = threadIdx.x;
    if (tid < 64) sAt[tid] = At[tid];
    __syncthreads();

    const int g  = tid >> 6, f = tid & 63;
    const int bx = blockIdx.x * 4 + g;      // 0..3999
    const int b  = bx / 500;
    const int s  = bx - b * 500;

    const size_t base = (size_t)s * CN + b * (T_DIM * FO) + f;
    const size_t m2off = (size_t)KP * CN;

    float m0[8], m1v[8], m2v[8];
    #pragma unroll
    for (int t = 0; t < 8; t++) {
        m0[t]  = g_Z[base + t * 64];
        m1v[t] = g_C[base + t * 64];
        m2v[t] = g_C[m2off + base + t * 64];
    }
    const float s0 = sv[0], s1 = sv[1], s2 = sv[2], s3 = sv[3];
    const float c00 = s0 * s0, c01 = 2.f * s0 * s1, c02 = s1 * s1;
    const float c10 = 2.f * s0 * s2, c11 = 2.f * (s0 * s3 + s1 * s2), c12 = 2.f * s1 * s3;
    const float c20 = s2 * s2, c21 = 2.f * s2 * s3, c22 = s3 * s3;

    float n10[8], n11[8], n12[8];
    #pragma unroll
    for (int t = 0; t < 8; t++) {
        float a0 = 0.f, a1 = 0.f, a2 = 0.f;
        #pragma unroll
        for (int u = 0; u < 8; u++) {
            const float w = sAt[t * 8 + u];
            a0 += w * m0[u]; a1 += w * m1v[u]; a2 += w * m2v[u];
        }
        n10[t] = a0; n11[t] = a1; n12[t] = a2;
    }
    #pragma unroll
    for (int t = 0; t < 8; t++) {
        float a0 = 0.f, a1 = 0.f, a2 = 0.f;
        #pragma unroll
        for (int u = 0; u < 8; u++) {
            const float w = sAt[t * 8 + u];
            a0 += w * n10[u]; a1 += w * n11[u]; a2 += w * n12[u];
        }
        const float y1 = s0 * m0[t] + s1 * m1v[t] + s2 * n10[t] + s3 * n11[t];
        const float y2 = c00 * m0[t] + c01 * m1v[t] + c02 * m2v[t]
                       + c10 * n10[t] + c11 * n11[t] + c12 * n12[t]
                       + c20 * a0 + c21 * a1 + c22 * a2;

        __half* ap = g_A2 + (size_t)(s * 64 + b * 8 + t) * K2A;
        __half h, lo;
        split_h(m0[t], h, lo);  ap[f]       = h; ap[192 + f] = lo;
        split_h(y1, h, lo);     ap[64 + f]  = h; ap[256 + f] = lo;
        split_h(y2, h, lo);     ap[128 + f] = h; ap[320 + f] = lo;
    }
}

// ---------------------------------------------------------------------------
// k_out
// ---------------------------------------------------------------------------
__global__ __launch_bounds__(64)
void k_out(const float* __restrict__ W2, const float* __restrict__ b2,
           const float* __restrict__ merge, float* __restrict__ out)
{
    __shared__ float su[64];
    __shared__ float sm[8];
    const int tid = threadIdx.x;
    const int bx  = blockIdx.x;
    const int b   = bx / 500;
    const int s   = bx - b * 500;
    if (tid < 8) sm[tid] = merge[tid];
    __syncthreads();

    const size_t base = (size_t)s * CN + b * (T_DIM * FO) + tid;
    float acc = 0.f, msum = 0.f;
    #pragma unroll
    for (int t = 0; t < 8; t++) {
        acc  += sm[t] * g_Z[base + t * 64];
        msum += sm[t];
    }
    su[tid] = acc;
    __syncthreads();

    float o = msum * b2[tid];
    const float* w = W2 + tid * 64;
    #pragma unroll 8
    for (int f = 0; f < 64; f++) o += w[f] * su[f];
    out[bx * 64 + tid] = o;
}

// ---------------------------------------------------------------------------
extern "C" void kernel_launch(void* const* d_in, const int* in_sizes, int n_in,
                              void* d_out, int out_size)
{
    const float* x     = (const float*)d_in[0];
    const float* At    = (const float*)d_in[1];
    const float* As    = (const float*)d_in[2];
    const float* sv    = (const float*)d_in[3];
    const float* H     = (const float*)d_in[4];
    const float* W1    = (const float*)d_in[5];
    const float* b1    = (const float*)d_in[6];
    const float* W2    = (const float*)d_in[7];
    const float* b2    = (const float*)d_in[8];
    const float* merge = (const float*)d_in[9];
    float* out = (float*)d_out;

    const int SM_MAIN = 2 * (2 * ATILE_B);               // 73728
    const int SM_MIX  = 2 * (ATILE_B + BTILE2_B);        // 55296
    cudaFuncSetAttribute(tg_main, cudaFuncAttributeMaxDynamicSharedMemorySize, SM_MAIN);
    cudaFuncSetAttribute(tg_mix,  cudaFuncAttributeMaxDynamicSharedMemorySize, SM_MIX);

    __half *Abig, *BT, *Bhi, *A2, *Ht;
    float *Cp;
    cudaGetSymbolAddress((void**)&Abig, g_Abig);
    cudaGetSymbolAddress((void**)&BT,   g_BT);
    cudaGetSymbolAddress((void**)&Bhi,  g_Bhi);
    cudaGetSymbolAddress((void**)&A2,   g_A2);
    cudaGetSymbolAddress((void**)&Ht,   g_Ht);
    cudaGetSymbolAddress((void**)&Cp,   g_C);

    // 0: input projection (also emits fp16 B operand for layer 0)
    k_inproj<<<dim3(64, 10), 256>>>(x, W1, b1);
    // 1: As splits
    k_split_as<<<dim3(16, 16), 256>>>(As);
    // 2: As2 = As @ As, epilogue split-writes Abig rows 512+
    tg_main<<<dim3(4, 4), 256, SM_MAIN>>>(Abig, BT, Cp, KC, KP, 1);

    for (int l = 0; l < 3; l++) {
        if (l > 0) k_splitT_z<<<dim3(128, 16), 256>>>();
        // launch index 3 on l=0: the main GEMM (profiled)
        tg_main<<<dim3(32, 8), 256, SM_MAIN>>>(Abig, Bhi, Cp, KC, CN, 0);
        if (l == 0) k_ht<<<3, 256>>>(H);
        k_comb<<<1000, 256>>>(At, sv);
        tg_mix<<<250, 256, SM_MIX>>>(A2, Ht + (size_t)l * FO * K2A);
    }

    k_out<<<4000, 64>>>(W2, b2, merge, out);
}